// round 16
// baseline (speedup 1.0000x reference)
#include <cuda_runtime.h>
#include <cuda_bf16.h>
#include <cuda_fp16.h>
#include <cstdint>
#include <math.h>

#define B_   16
#define N_   4096
#define C_   1152
#define H_   16
#define HD_  72
#define KV2  144
#define MTOT (B_*N_)       // 65536
#define KA2  1224          // C_ + HD_  (gemm2 A width)

// ---------------- scratch (static device globals) --------------------------
__device__ __half g_q16[(size_t)MTOT * C_];       // fp16 q, 151 MB
__device__ float g_kvlin[(size_t)MTOT * KV2];     // 37.7 MB
__device__ float g_kv[B_ * HD_ * HD_];
__device__ float g_qsum[B_ * H_ * 2];
__device__ float g_ksum[B_ * 2];

__device__ __half g_X16[(size_t)MTOT * C_];       // fp16 x, 151 MB
__device__ __half g_Wqh[(size_t)C_ * C_];         // fp16 Wq^T  [n][k]
__device__ __half g_Wkvh[(size_t)KV2 * C_];       // fp16 Wkv^T [n][k]
__device__ __half g_A2h[(size_t)MTOT * KA2];      // [q3 | vd]  fp16
__device__ __half g_B2h[(size_t)B_ * C_ * KA2];   // [scaled Mt | Pt] fp16

// ====================== PTX helpers =========================================
__device__ __forceinline__ uint32_t smem_u32(const void* p) {
    uint32_t a;
    asm("{ .reg .u64 t; cvta.to.shared.u64 t, %1; cvt.u32.u64 %0, t; }" : "=r"(a) : "l"(p));
    return a;
}
__device__ __forceinline__ void cp16(uint32_t dst, const void* src, int sz) {
    asm volatile("cp.async.cg.shared.global [%0], [%1], 16, %2;"
                 :: "r"(dst), "l"(src), "r"(sz) : "memory");
}
__device__ __forceinline__ void cp_commit() { asm volatile("cp.async.commit_group;" ::: "memory"); }
template <int NN> __device__ __forceinline__ void cp_wait() {
    asm volatile("cp.async.wait_group %0;" :: "n"(NN) : "memory");
}
__device__ __forceinline__ uint32_t swz(uint32_t off) { return off ^ ((off >> 3) & 0x70); }

__device__ __forceinline__ void ldsm4(uint32_t* r, uint32_t addr) {
    asm volatile("ldmatrix.sync.aligned.m8n8.x4.shared.b16 {%0,%1,%2,%3}, [%4];"
        : "=r"(r[0]), "=r"(r[1]), "=r"(r[2]), "=r"(r[3]) : "r"(addr));
}
__device__ __forceinline__ void mma_bf16(float* c, const uint32_t* a, const uint32_t* b) {
    asm volatile("mma.sync.aligned.m16n8k16.row.col.f32.bf16.bf16.f32 "
        "{%0,%1,%2,%3}, {%4,%5,%6,%7}, {%8,%9}, {%0,%1,%2,%3};"
        : "+f"(c[0]), "+f"(c[1]), "+f"(c[2]), "+f"(c[3])
        : "r"(a[0]), "r"(a[1]), "r"(a[2]), "r"(a[3]), "r"(b[0]), "r"(b[1]));
}
__device__ __forceinline__ void mma_f16(float* c, const uint32_t* a, const uint32_t* b) {
    asm volatile("mma.sync.aligned.m16n8k16.row.col.f32.f16.f16.f32 "
        "{%0,%1,%2,%3}, {%4,%5,%6,%7}, {%8,%9}, {%0,%1,%2,%3};"
        : "+f"(c[0]), "+f"(c[1]), "+f"(c[2]), "+f"(c[3])
        : "r"(a[0]), "r"(a[1]), "r"(a[2]), "r"(a[3]), "r"(b[0]), "r"(b[1]));
}

#define SMEM_BYTES (1024 + 3 * 32768)

// ====================== staged tile fill (cp.async, SW128) ==================
template <typename T, int KA, int NPASS, int NTOT>
__device__ __forceinline__ void fill_stage(
    uint32_t sb, int s, int kt,
    const T* __restrict__ Ahi, const T* __restrict__ Alo,
    int arow0,
    const T* __restrict__ Bhi, const T* __restrict__ Blo,
    size_t boff, int n0) {
    const int K3 = NPASS * KA;
    uint32_t ab = sb + 1024u + (uint32_t)s * 32768u;
    uint32_t bb = ab + 16384u;
    int tid = threadIdx.x;
#pragma unroll
    for (int i = 0; i < 4; i++) {
        int q = tid + i * 256;
        int r = q >> 3, c16 = q & 7;
        int k3 = kt * 64 + c16 * 8;
        bool kin = k3 < K3;
        int pass = kin ? (k3 / KA) : 0;
        int kloc = kin ? (k3 - pass * KA) : 0;
        uint32_t sw = swz((uint32_t)(r * 128 + c16 * 16));
        const T* asrc = (pass == 1 ? Alo : Ahi) + (size_t)(arow0 + r) * KA + kloc;
        cp16(ab + sw, asrc, kin ? 16 : 0);
        int n = n0 + r;
        bool bin = kin && (n < NTOT);
        const T* bsrc = (pass == 2 ? Blo : Bhi) + boff + (size_t)(bin ? n : 0) * KA + kloc;
        cp16(bb + sw, bsrc, bin ? 16 : 0);
    }
}

// ====================== HMMA GEMM ===========================================
// Structure frozen (r12 body + r15 2-CTA bound). HALF_OUT only swaps the
// store instruction in the non-KV epilogue path — no extra live state.
// KV_OUT : out1[row*KV2 + col] = acc + bias1[col]  (col < KV2 only)
// HALF_OUT: ((half*)out0)[row*C_ + col] = half(acc + bias0[col])
// else   : out0[row*C_ + col] = acc + bias0[col]
template <typename T, int KA, int KT, int NPASS, int NTOT,
          bool KV_OUT, bool FP16, bool HALF_OUT>
__global__ __launch_bounds__(256, 2) void k_hgemm(
    const T* __restrict__ Ahi, const T* __restrict__ Alo,
    const T* __restrict__ Bhi, const T* __restrict__ Blo,
    float* __restrict__ out0, float* __restrict__ out1,
    const float* __restrict__ bias0, const float* __restrict__ bias1) {
    extern __shared__ char smem[];
    uint32_t sb = smem_u32(smem);
    int tid = threadIdx.x;
    int lane = tid & 31, warp = tid >> 5;
    int wm = warp & 1, wn = warp >> 1;        // warp grid 2 x 4
    int mi = lane >> 3, r8 = lane & 7;

    int n0 = blockIdx.x * 128;
    int arow0 = (int)(blockIdx.z * 4096 + blockIdx.y * 128);
    size_t boff = (size_t)blockIdx.z * NTOT * KA;

    int a_row = wm * 64 + (mi & 1) * 8 + r8;
    int a_k8  = (mi >> 1) * 8;
    int b_row = wn * 32 + (mi >> 1) * 8 + r8;
    int b_k8  = (mi & 1) * 8;

    float acc[16][4];
#pragma unroll
    for (int i = 0; i < 16; i++)
#pragma unroll
        for (int j = 0; j < 4; j++) acc[i][j] = 0.f;

    fill_stage<T, KA, NPASS, NTOT>(sb, 0, 0, Ahi, Alo, arow0, Bhi, Blo, boff, n0); cp_commit();
    fill_stage<T, KA, NPASS, NTOT>(sb, 1, 1, Ahi, Alo, arow0, Bhi, Blo, boff, n0); cp_commit();

    for (int kt = 0; kt < KT; kt++) {
        int buf = kt % 3;
        if (kt + 2 < KT) {
            fill_stage<T, KA, NPASS, NTOT>(sb, (kt + 2) % 3, kt + 2, Ahi, Alo, arow0,
                                           Bhi, Blo, boff, n0);
            cp_commit();
            cp_wait<2>();
        } else if (kt + 1 < KT) {
            cp_wait<1>();
        } else {
            cp_wait<0>();
        }
        __syncthreads();

        uint32_t ab = sb + 1024u + (uint32_t)buf * 32768u;
        uint32_t bb = ab + 16384u;
#pragma unroll
        for (int kk = 0; kk < 4; kk++) {
            uint32_t afr[4][4], bfr[2][4];
#pragma unroll
            for (int mt = 0; mt < 4; mt++)
                ldsm4(afr[mt], ab + swz((uint32_t)((a_row + mt * 16) * 128
                                                   + (kk * 16 + a_k8) * 2)));
#pragma unroll
            for (int bt = 0; bt < 2; bt++)
                ldsm4(bfr[bt], bb + swz((uint32_t)((b_row + bt * 16) * 128
                                                   + (kk * 16 + b_k8) * 2)));
#pragma unroll
            for (int mt = 0; mt < 4; mt++)
#pragma unroll
                for (int nt = 0; nt < 4; nt++) {
                    if (FP16) mma_f16(acc[mt * 4 + nt], afr[mt], &bfr[nt >> 1][(nt & 1) * 2]);
                    else      mma_bf16(acc[mt * 4 + nt], afr[mt], &bfr[nt >> 1][(nt & 1) * 2]);
                }
        }
        __syncthreads();
    }

    // ---- epilogue: fragment -> global, bias add only ----
    int crow = lane >> 2, ccol = (lane & 3) * 2;
#pragma unroll
    for (int mt = 0; mt < 4; mt++) {
#pragma unroll
        for (int nt = 0; nt < 4; nt++) {
            int col = n0 + wn * 32 + nt * 8 + ccol;
            const float* cp = acc[mt * 4 + nt];
#pragma unroll
            for (int half = 0; half < 2; half++) {
                int row = arow0 + wm * 64 + mt * 16 + crow + half * 8;
                float v0 = cp[half * 2], v1 = cp[half * 2 + 1];
                if (KV_OUT) {
                    if (col < KV2) {
                        float2 o = make_float2(v0 + bias1[col], v1 + bias1[col + 1]);
                        *(float2*)&out1[(size_t)row * KV2 + col] = o;
                    }
                } else if (HALF_OUT) {
                    __half2 o = __halves2half2(__float2half(v0 + bias0[col]),
                                               __float2half(v1 + bias0[col + 1]));
                    *(__half2*)&((__half*)out0)[(size_t)row * C_ + col] = o;
                } else {
                    float2 o = make_float2(v0 + bias0[col], v1 + bias0[col + 1]);
                    *(float2*)&out0[(size_t)row * C_ + col] = o;
                }
            }
        }
    }
}

// ====================== convert / precompute kernels ========================
__global__ void k_xcvt(const float* __restrict__ x) {
    size_t i = (size_t)blockIdx.x * 256 + threadIdx.x;
    g_X16[i] = __float2half(x[i]);
}

__global__ void k_wcvt(const float* __restrict__ wq, const float* __restrict__ wkv) {
    int i = blockIdx.x * 256 + threadIdx.x;           // over 1296*C_
    int n = i / C_, k = i - n * C_;
    if (n < C_)
        g_Wqh[(size_t)n * C_ + k] = __float2half(wq[(size_t)k * C_ + n]);
    else
        g_Wkvh[(size_t)(n - C_) * C_ + k] = __float2half(wkv[(size_t)k * KV2 + (n - C_)]);
}

// ---------------- init ------------------------------------------------------
__global__ void k_init() {
    int i = blockIdx.x * blockDim.x + threadIdx.x;
    if (i < B_ * HD_ * HD_) g_kv[i] = 0.f;
    if (i < B_ * H_ * 2)    g_qsum[i] = 0.f;
    if (i < B_ * 2)         g_ksum[i] = 0.f;
}

// ---------------- block reduce two floats (256 thr) --------------------------
__device__ __forceinline__ void block_reduce2(float& s2, float& s6) {
#pragma unroll
    for (int o = 16; o; o >>= 1) {
        s2 += __shfl_down_sync(0xffffffffu, s2, o);
        s6 += __shfl_down_sync(0xffffffffu, s6, o);
    }
    __shared__ float sh2[8], sh6[8];
    int w = threadIdx.x >> 5, l = threadIdx.x & 31;
    if (l == 0) { sh2[w] = s2; sh6[w] = s6; }
    __syncthreads();
    if (threadIdx.x == 0) {
        float a = 0.f, c = 0.f;
#pragma unroll
        for (int i = 0; i < 8; i++) { a += sh2[i]; c += sh6[i]; }
        s2 = a; s6 = c;
    }
}

// ---------------- q: relu^3 -> A2 (fp16, unscaled) + norm sums, one pass ----
// grid 4096 = (bh 256) x (split 16); block 256    (reads fp16 q now)
__global__ void k_qf3norm() {
    int bh = blockIdx.x >> 4;
    int split = blockIdx.x & 15;
    int b = bh >> 4, h = bh & 15;
    size_t row0 = (size_t)(b * N_ + split * 256);
    const __half* base = g_q16 + row0 * C_ + h * HD_;
    __half* ah = g_A2h + row0 * KA2 + h * HD_;
    float s2 = 0.f, s6 = 0.f;
    for (int e = threadIdx.x; e < 256 * HD_; e += 256) {
        int r = e / HD_, d = e % HD_;
        float v = __half2float(base[(size_t)r * C_ + d]);
        float rr = fmaxf(v, 0.f);
        float p = rr * rr;
        float t = p * rr;
        s2 += p; s6 += t * t;
        ah[(size_t)r * KA2 + d] = __float2half(t);
    }
    block_reduce2(s2, s6);
    if (threadIdx.x == 0) {
        atomicAdd(&g_qsum[bh * 2], s2);
        atomicAdd(&g_qsum[bh * 2 + 1], s6);
    }
}

// ---------------- kv = k3^T @ v (unscaled) + fused k norms --------------------
// grid (8 nsplits, 16 b), block 576
__global__ __launch_bounds__(576) void k_kvacc() {
    __shared__ float ks[16][72], vs[16][72];
    __shared__ float rsh2[18], rsh6[18];
    int b = blockIdx.y;
    int n0 = blockIdx.x * 512;
    int tid = threadIdx.x;
    float acc[9] = {};
    float k2 = 0.f, k6 = 0.f;
    int od[9], oe[9];
#pragma unroll
    for (int j = 0; j < 9; j++) { int o = tid + j * 576; od[j] = o / 72; oe[j] = o % 72; }

    for (int nt = 0; nt < 512; nt += 16) {
        __syncthreads();
        for (int e = tid; e < 16 * 72; e += 576) {
            int r = e / 72, d = e % 72;
            const float* p = g_kvlin + (size_t)(b * N_ + n0 + nt + r) * KV2;
            float kvv = p[d];
            float rr = fmaxf(kvv, 0.f);
            float p2 = rr * rr;
            float t = p2 * rr;
            ks[r][d] = t;
            vs[r][d] = p[72 + d];
            k2 += p2; k6 += t * t;
        }
        __syncthreads();
#pragma unroll
        for (int r = 0; r < 16; r++)
#pragma unroll
            for (int j = 0; j < 9; j++) acc[j] += ks[r][od[j]] * vs[r][oe[j]];
    }
#pragma unroll
    for (int j = 0; j < 9; j++)
        atomicAdd(&g_kv[b * 5184 + tid + j * 576], acc[j]);

#pragma unroll
    for (int o = 16; o; o >>= 1) {
        k2 += __shfl_down_sync(0xffffffffu, k2, o);
        k6 += __shfl_down_sync(0xffffffffu, k6, o);
    }
    int w = tid >> 5, l = tid & 31;
    if (l == 0) { rsh2[w] = k2; rsh6[w] = k6; }
    __syncthreads();
    if (tid == 0) {
        float a = 0.f, c = 0.f;
#pragma unroll
        for (int i = 0; i < 18; i++) { a += rsh2[i]; c += rsh6[i]; }
        atomicAdd(&g_ksum[b * 2], a);
        atomicAdd(&g_ksum[b * 2 + 1], c);
    }
}

// ---------------- depthwise conv -> A2 cols [C_, KA2) (fp16) -----------------
__global__ void k_dwc(const float* __restrict__ w, const float* __restrict__ bias) {
    int idx = blockIdx.x * blockDim.x + threadIdx.x;
    int d = idx % HD_;
    int t = idx / HD_;
    int n = t % N_;
    int b = t / N_;
    int y = n >> 6, xx = n & 63;
    float acc = bias[d];
#pragma unroll
    for (int ky = 0; ky < 3; ky++) {
        int yy = y + ky - 1;
        if ((unsigned)yy < 64u) {
#pragma unroll
            for (int kx = 0; kx < 3; kx++) {
                int xc = xx + kx - 1;
                if ((unsigned)xc < 64u)
                    acc += g_kvlin[(size_t)(b * N_ + yy * 64 + xc) * KV2 + 72 + d]
                         * w[d * 9 + ky * 3 + kx];
            }
        }
    }
    g_A2h[(size_t)(b * N_ + n) * KA2 + C_ + d] = __float2half(acc);
}

// ---------------- proj_sum -> B2 rows [C_, KA2) (fp16) -----------------------
__global__ void k_projsum(const float* __restrict__ proj) {
    int idx = blockIdx.x * blockDim.x + threadIdx.x;   // 72*1152
    if (idx >= HD_ * C_) return;
    int c = idx / HD_, d = idx % HD_;
    float s = 0.f;
#pragma unroll
    for (int h = 0; h < H_; h++) s += proj[(size_t)(h * HD_ + d) * C_ + c];
    __half hv = __float2half(s);
#pragma unroll
    for (int b = 0; b < B_; b++)
        g_B2h[((size_t)b * C_ + c) * KA2 + C_ + d] = hv;
}

// Mt[b][c][h*72+d] = scaleq[b,h]*scalek[b] * sum_e kv[b][d][e]*proj[h*72+e][c]
__global__ __launch_bounds__(256) void k_mker(const float* __restrict__ proj) {
    __shared__ float kvs[72 * 72];
    int b = blockIdx.z, h = blockIdx.y, ct = blockIdx.x;
    int tid = threadIdx.x;
    for (int e = tid; e < 5184; e += 256) kvs[e] = g_kv[b * 5184 + e];
    __syncthreads();
    int c = ct * 128 + (tid & 127);
    int dbase = (tid >> 7) * 36;
    float acc[36] = {};
#pragma unroll 8
    for (int e2 = 0; e2 < 72; e2++) {
        float p = proj[(size_t)(h * HD_ + e2) * C_ + c];
#pragma unroll
        for (int dd = 0; dd < 36; dd++)
            acc[dd] += kvs[(dbase + dd) * 72 + e2] * p;
    }
    float q2 = g_qsum[(b * H_ + h) * 2], q6 = g_qsum[(b * H_ + h) * 2 + 1];
    float kk2 = g_ksum[b * 2], kk6 = g_ksum[b * 2 + 1];
    float sq = ((q6 > 0.f) ? sqrtf(q2 / q6) : 0.f)
             * ((kk6 > 0.f) ? sqrtf(kk2 / kk6) : 0.f);
    size_t base = ((size_t)b * C_ + c) * KA2 + h * HD_ + dbase;
#pragma unroll
    for (int dd = 0; dd < 36; dd++)
        g_B2h[base + dd] = __float2half(acc[dd] * sq);
}

// ---------------- launch ------------------------------------------------------
extern "C" void kernel_launch(void* const* d_in, const int* in_sizes, int n_in,
                              void* d_out, int out_size) {
    const float* x      = (const float*)d_in[0];
    const float* wq_w   = (const float*)d_in[1];
    const float* wq_b   = (const float*)d_in[2];
    const float* wkv_w  = (const float*)d_in[3];
    const float* wkv_b  = (const float*)d_in[4];
    const float* dwc_w  = (const float*)d_in[5];
    const float* dwc_b  = (const float*)d_in[6];
    const float* proj_w = (const float*)d_in[7];
    const float* proj_b = (const float*)d_in[8];
    float* out = (float*)d_out;

    cudaFuncSetAttribute(
        k_hgemm<__half, C_, 18, 1, C_, false, true, true>,
        cudaFuncAttributeMaxDynamicSharedMemorySize, SMEM_BYTES);
    cudaFuncSetAttribute(
        k_hgemm<__half, C_, 18, 1, KV2, true, true, false>,
        cudaFuncAttributeMaxDynamicSharedMemorySize, SMEM_BYTES);
    cudaFuncSetAttribute(
        k_hgemm<__half, KA2, 20, 1, C_, false, true, false>,
        cudaFuncAttributeMaxDynamicSharedMemorySize, SMEM_BYTES);

    __half *x16, *wqh, *wkvh, *a2h, *b2h, *q16;
    float *gkvlin;
    cudaGetSymbolAddress((void**)&x16,  g_X16);
    cudaGetSymbolAddress((void**)&wqh,  g_Wqh);
    cudaGetSymbolAddress((void**)&wkvh, g_Wkvh);
    cudaGetSymbolAddress((void**)&a2h,  g_A2h);
    cudaGetSymbolAddress((void**)&b2h,  g_B2h);
    cudaGetSymbolAddress((void**)&q16,  g_q16);
    cudaGetSymbolAddress((void**)&gkvlin, g_kvlin);

    k_init<<<324, 256>>>();
    k_xcvt<<<(int)((MTOT * (size_t)C_) / 256), 256>>>(x);
    k_wcvt<<<((C_ + KV2) * C_) / 256, 256>>>(wq_w, wkv_w);

    // q-GEMM: x @ wq -> g_q16 (fp16 out)   (fp16 single-pass, K=1152, KT=18)
    k_hgemm<__half, C_, 18, 1, C_, false, true, true>
        <<<dim3(9, 512, 1), 256, SMEM_BYTES>>>(
            x16, x16, wqh, wqh, (float*)q16, nullptr, wq_b, nullptr);

    // kv-GEMM: x @ wkv -> g_kvlin   (fp16 single-pass, K=1152, KT=18)
    k_hgemm<__half, C_, 18, 1, KV2, true, true, false>
        <<<dim3(2, 512, 1), 256, SMEM_BYTES>>>(
            x16, x16, wkvh, wkvh, nullptr, gkvlin, nullptr, wkv_b);

    k_qf3norm<<<4096, 256>>>();        // q3 (fp16) -> A2 + qsum (one pass)
    k_kvacc<<<dim3(8, 16), 576>>>();   // kv accum + fused ksum
    k_dwc<<<18432, 256>>>(dwc_w, dwc_b);
    k_projsum<<<324, 256>>>(proj_w);
    k_mker<<<dim3(9, 16, 16), 256>>>(proj_w);   // inline scales, folds sq*sk

    // GEMM2: [q3|vd] @ [scaled Mt|Pt]^T + proj_b -> out  (fp16, K=1224, KT=20)
    k_hgemm<__half, KA2, 20, 1, C_, false, true, false>
        <<<dim3(9, 32, 16), 256, SMEM_BYTES>>>(
            a2h, a2h, b2h, b2h, out, nullptr, proj_b, nullptr);
}

// round 17
// speedup vs baseline: 1.1141x; 1.1141x over previous
#include <cuda_runtime.h>
#include <cuda_bf16.h>
#include <cuda_fp16.h>
#include <cstdint>
#include <math.h>

#define B_   16
#define N_   4096
#define C_   1152
#define H_   16
#define HD_  72
#define KV2  144
#define MTOT (B_*N_)       // 65536
#define KA2  1224          // C_ + HD_  (gemm2 A width)

// ---------------- scratch (static device globals) --------------------------
__device__ float g_q[(size_t)MTOT * C_];          // 302 MB
__device__ float g_kvlin[(size_t)MTOT * KV2];     // 37.7 MB
__device__ float g_kv[B_ * HD_ * HD_];
__device__ float g_qsum[B_ * H_ * 2];
__device__ float g_ksum[B_ * 2];

__device__ __half g_X16[(size_t)MTOT * C_];       // fp16 x, 151 MB
__device__ __half g_Wqh[(size_t)C_ * C_];         // fp16 Wq^T  [n][k]
__device__ __half g_Wkvh[(size_t)KV2 * C_];       // fp16 Wkv^T [n][k]
__device__ __half g_A2h[(size_t)MTOT * KA2];      // [q3 | vd]  fp16
__device__ __half g_B2h[(size_t)B_ * C_ * KA2];   // [scaled Mt | Pt] fp16

// ====================== PTX helpers =========================================
__device__ __forceinline__ uint32_t smem_u32(const void* p) {
    uint32_t a;
    asm("{ .reg .u64 t; cvta.to.shared.u64 t, %1; cvt.u32.u64 %0, t; }" : "=r"(a) : "l"(p));
    return a;
}
__device__ __forceinline__ void cp16(uint32_t dst, const void* src, int sz) {
    asm volatile("cp.async.cg.shared.global [%0], [%1], 16, %2;"
                 :: "r"(dst), "l"(src), "r"(sz) : "memory");
}
__device__ __forceinline__ void cp_commit() { asm volatile("cp.async.commit_group;" ::: "memory"); }
template <int NN> __device__ __forceinline__ void cp_wait() {
    asm volatile("cp.async.wait_group %0;" :: "n"(NN) : "memory");
}
__device__ __forceinline__ uint32_t swz(uint32_t off) { return off ^ ((off >> 3) & 0x70); }

__device__ __forceinline__ void ldsm4(uint32_t* r, uint32_t addr) {
    asm volatile("ldmatrix.sync.aligned.m8n8.x4.shared.b16 {%0,%1,%2,%3}, [%4];"
        : "=r"(r[0]), "=r"(r[1]), "=r"(r[2]), "=r"(r[3]) : "r"(addr));
}
__device__ __forceinline__ void mma_bf16(float* c, const uint32_t* a, const uint32_t* b) {
    asm volatile("mma.sync.aligned.m16n8k16.row.col.f32.bf16.bf16.f32 "
        "{%0,%1,%2,%3}, {%4,%5,%6,%7}, {%8,%9}, {%0,%1,%2,%3};"
        : "+f"(c[0]), "+f"(c[1]), "+f"(c[2]), "+f"(c[3])
        : "r"(a[0]), "r"(a[1]), "r"(a[2]), "r"(a[3]), "r"(b[0]), "r"(b[1]));
}
__device__ __forceinline__ void mma_f16(float* c, const uint32_t* a, const uint32_t* b) {
    asm volatile("mma.sync.aligned.m16n8k16.row.col.f32.f16.f16.f32 "
        "{%0,%1,%2,%3}, {%4,%5,%6,%7}, {%8,%9}, {%0,%1,%2,%3};"
        : "+f"(c[0]), "+f"(c[1]), "+f"(c[2]), "+f"(c[3])
        : "r"(a[0]), "r"(a[1]), "r"(a[2]), "r"(a[3]), "r"(b[0]), "r"(b[1]));
}

#define SMEM_BYTES (1024 + 3 * 32768)

// ====================== staged tile fill (cp.async, SW128) ==================
template <typename T, int KA, int NPASS, int NTOT>
__device__ __forceinline__ void fill_stage(
    uint32_t sb, int s, int kt,
    const T* __restrict__ Ahi, const T* __restrict__ Alo,
    int arow0,
    const T* __restrict__ Bhi, const T* __restrict__ Blo,
    size_t boff, int n0) {
    const int K3 = NPASS * KA;
    uint32_t ab = sb + 1024u + (uint32_t)s * 32768u;
    uint32_t bb = ab + 16384u;
    int tid = threadIdx.x;
#pragma unroll
    for (int i = 0; i < 4; i++) {
        int q = tid + i * 256;
        int r = q >> 3, c16 = q & 7;
        int k3 = kt * 64 + c16 * 8;
        bool kin = k3 < K3;
        int pass = kin ? (k3 / KA) : 0;
        int kloc = kin ? (k3 - pass * KA) : 0;
        uint32_t sw = swz((uint32_t)(r * 128 + c16 * 16));
        const T* asrc = (pass == 1 ? Alo : Ahi) + (size_t)(arow0 + r) * KA + kloc;
        cp16(ab + sw, asrc, kin ? 16 : 0);
        int n = n0 + r;
        bool bin = kin && (n < NTOT);
        const T* bsrc = (pass == 2 ? Blo : Bhi) + boff + (size_t)(bin ? n : 0) * KA + kloc;
        cp16(bb + sw, bsrc, bin ? 16 : 0);
    }
}

// ====================== HMMA GEMM ===========================================
// FROZEN r15 binary: r12 body + __launch_bounds__(256,2). Only template
// arguments may change.
// KV_OUT=false: out0[row*C_ + col] = acc + bias0[col]
// KV_OUT=true : out1[row*KV2 + col] = acc + bias1[col]  (col < KV2 only)
template <typename T, int KA, int KT, int NPASS, int NTOT, bool KV_OUT, bool FP16>
__global__ __launch_bounds__(256, 2) void k_hgemm(
    const T* __restrict__ Ahi, const T* __restrict__ Alo,
    const T* __restrict__ Bhi, const T* __restrict__ Blo,
    float* __restrict__ out0, float* __restrict__ out1,
    const float* __restrict__ bias0, const float* __restrict__ bias1) {
    extern __shared__ char smem[];
    uint32_t sb = smem_u32(smem);
    int tid = threadIdx.x;
    int lane = tid & 31, warp = tid >> 5;
    int wm = warp & 1, wn = warp >> 1;        // warp grid 2 x 4
    int mi = lane >> 3, r8 = lane & 7;

    int n0 = blockIdx.x * 128;
    int arow0 = (int)(blockIdx.z * 4096 + blockIdx.y * 128);
    size_t boff = (size_t)blockIdx.z * NTOT * KA;

    int a_row = wm * 64 + (mi & 1) * 8 + r8;
    int a_k8  = (mi >> 1) * 8;
    int b_row = wn * 32 + (mi >> 1) * 8 + r8;
    int b_k8  = (mi & 1) * 8;

    float acc[16][4];
#pragma unroll
    for (int i = 0; i < 16; i++)
#pragma unroll
        for (int j = 0; j < 4; j++) acc[i][j] = 0.f;

    fill_stage<T, KA, NPASS, NTOT>(sb, 0, 0, Ahi, Alo, arow0, Bhi, Blo, boff, n0); cp_commit();
    fill_stage<T, KA, NPASS, NTOT>(sb, 1, 1, Ahi, Alo, arow0, Bhi, Blo, boff, n0); cp_commit();

    for (int kt = 0; kt < KT; kt++) {
        int buf = kt % 3;
        if (kt + 2 < KT) {
            fill_stage<T, KA, NPASS, NTOT>(sb, (kt + 2) % 3, kt + 2, Ahi, Alo, arow0,
                                           Bhi, Blo, boff, n0);
            cp_commit();
            cp_wait<2>();
        } else if (kt + 1 < KT) {
            cp_wait<1>();
        } else {
            cp_wait<0>();
        }
        __syncthreads();

        uint32_t ab = sb + 1024u + (uint32_t)buf * 32768u;
        uint32_t bb = ab + 16384u;
#pragma unroll
        for (int kk = 0; kk < 4; kk++) {
            uint32_t afr[4][4], bfr[2][4];
#pragma unroll
            for (int mt = 0; mt < 4; mt++)
                ldsm4(afr[mt], ab + swz((uint32_t)((a_row + mt * 16) * 128
                                                   + (kk * 16 + a_k8) * 2)));
#pragma unroll
            for (int bt = 0; bt < 2; bt++)
                ldsm4(bfr[bt], bb + swz((uint32_t)((b_row + bt * 16) * 128
                                                   + (kk * 16 + b_k8) * 2)));
#pragma unroll
            for (int mt = 0; mt < 4; mt++)
#pragma unroll
                for (int nt = 0; nt < 4; nt++) {
                    if (FP16) mma_f16(acc[mt * 4 + nt], afr[mt], &bfr[nt >> 1][(nt & 1) * 2]);
                    else      mma_bf16(acc[mt * 4 + nt], afr[mt], &bfr[nt >> 1][(nt & 1) * 2]);
                }
        }
        __syncthreads();
    }

    // ---- epilogue: fragment -> global (float2 stores), bias add only ----
    int crow = lane >> 2, ccol = (lane & 3) * 2;
#pragma unroll
    for (int mt = 0; mt < 4; mt++) {
#pragma unroll
        for (int nt = 0; nt < 4; nt++) {
            int col = n0 + wn * 32 + nt * 8 + ccol;
            const float* cp = acc[mt * 4 + nt];
#pragma unroll
            for (int half = 0; half < 2; half++) {
                int row = arow0 + wm * 64 + mt * 16 + crow + half * 8;
                float v0 = cp[half * 2], v1 = cp[half * 2 + 1];
                if (KV_OUT) {
                    if (col < KV2) {
                        float2 o = make_float2(v0 + bias1[col], v1 + bias1[col + 1]);
                        *(float2*)&out1[(size_t)row * KV2 + col] = o;
                    }
                } else {
                    float2 o = make_float2(v0 + bias0[col], v1 + bias0[col + 1]);
                    *(float2*)&out0[(size_t)row * C_ + col] = o;
                }
            }
        }
    }
}

// ====================== convert / precompute kernels ========================
// Vectorized: float4 in, 2x half2 out (4 elems/thread)
__global__ void k_xcvt(const float* __restrict__ x) {
    size_t i4 = (size_t)blockIdx.x * 256 + threadIdx.x;
    float4 v = ((const float4*)x)[i4];
    __half2 lo = __halves2half2(__float2half(v.x), __float2half(v.y));
    __half2 hi = __halves2half2(__float2half(v.z), __float2half(v.w));
    ((__half2*)g_X16)[i4 * 2]     = lo;
    ((__half2*)g_X16)[i4 * 2 + 1] = hi;
}

__global__ void k_wcvt(const float* __restrict__ wq, const float* __restrict__ wkv) {
    int i = blockIdx.x * 256 + threadIdx.x;           // over 1296*C_
    int n = i / C_, k = i - n * C_;
    if (n < C_)
        g_Wqh[(size_t)n * C_ + k] = __float2half(wq[(size_t)k * C_ + n]);
    else
        g_Wkvh[(size_t)(n - C_) * C_ + k] = __float2half(wkv[(size_t)k * KV2 + (n - C_)]);
}

// ---------------- init ------------------------------------------------------
__global__ void k_init() {
    int i = blockIdx.x * blockDim.x + threadIdx.x;
    if (i < B_ * HD_ * HD_) g_kv[i] = 0.f;
    if (i < B_ * H_ * 2)    g_qsum[i] = 0.f;
    if (i < B_ * 2)         g_ksum[i] = 0.f;
}

// ---------------- block reduce two floats (256 thr) --------------------------
__device__ __forceinline__ void block_reduce2(float& s2, float& s6) {
#pragma unroll
    for (int o = 16; o; o >>= 1) {
        s2 += __shfl_down_sync(0xffffffffu, s2, o);
        s6 += __shfl_down_sync(0xffffffffu, s6, o);
    }
    __shared__ float sh2[8], sh6[8];
    int w = threadIdx.x >> 5, l = threadIdx.x & 31;
    if (l == 0) { sh2[w] = s2; sh6[w] = s6; }
    __syncthreads();
    if (threadIdx.x == 0) {
        float a = 0.f, c = 0.f;
#pragma unroll
        for (int i = 0; i < 8; i++) { a += sh2[i]; c += sh6[i]; }
        s2 = a; s6 = c;
    }
}

// ---------------- q: relu^3 -> A2 (fp16, unscaled) + norm sums, vectorized ---
// grid 4096 = (bh 256) x (split 16); block 256; float4 over d (72/4=18 chunks)
__global__ void k_qf3norm() {
    int bh = blockIdx.x >> 4;
    int split = blockIdx.x & 15;
    int b = bh >> 4, h = bh & 15;
    size_t row0 = (size_t)(b * N_ + split * 256);
    const float* base = g_q + row0 * C_ + h * HD_;
    __half* ah = g_A2h + row0 * KA2 + h * HD_;
    float s2 = 0.f, s6 = 0.f;
    for (int e = threadIdx.x; e < 256 * 18; e += 256) {
        int r = e / 18, d4 = (e % 18) * 4;
        float4 v = *(const float4*)&base[(size_t)r * C_ + d4];
        float r0 = fmaxf(v.x, 0.f), r1 = fmaxf(v.y, 0.f);
        float r2 = fmaxf(v.z, 0.f), r3 = fmaxf(v.w, 0.f);
        float p0 = r0 * r0, p1 = r1 * r1, p2 = r2 * r2, p3 = r3 * r3;
        float t0 = p0 * r0, t1 = p1 * r1, t2 = p2 * r2, t3 = p3 * r3;
        s2 += p0 + p1 + p2 + p3;
        s6 += t0 * t0 + t1 * t1 + t2 * t2 + t3 * t3;
        __half2 lo = __halves2half2(__float2half(t0), __float2half(t1));
        __half2 hi = __halves2half2(__float2half(t2), __float2half(t3));
        __half2* dst = (__half2*)&ah[(size_t)r * KA2 + d4];
        dst[0] = lo; dst[1] = hi;
    }
    block_reduce2(s2, s6);
    if (threadIdx.x == 0) {
        atomicAdd(&g_qsum[bh * 2], s2);
        atomicAdd(&g_qsum[bh * 2 + 1], s6);
    }
}

// ---------------- kv = k3^T @ v (unscaled) + fused k norms --------------------
// grid (8 nsplits, 16 b), block 576
__global__ __launch_bounds__(576) void k_kvacc() {
    __shared__ float ks[16][72], vs[16][72];
    __shared__ float rsh2[18], rsh6[18];
    int b = blockIdx.y;
    int n0 = blockIdx.x * 512;
    int tid = threadIdx.x;
    float acc[9] = {};
    float k2 = 0.f, k6 = 0.f;
    int od[9], oe[9];
#pragma unroll
    for (int j = 0; j < 9; j++) { int o = tid + j * 576; od[j] = o / 72; oe[j] = o % 72; }

    for (int nt = 0; nt < 512; nt += 16) {
        __syncthreads();
        for (int e = tid; e < 16 * 72; e += 576) {
            int r = e / 72, d = e % 72;
            const float* p = g_kvlin + (size_t)(b * N_ + n0 + nt + r) * KV2;
            float kvv = p[d];
            float rr = fmaxf(kvv, 0.f);
            float p2 = rr * rr;
            float t = p2 * rr;
            ks[r][d] = t;
            vs[r][d] = p[72 + d];
            k2 += p2; k6 += t * t;
        }
        __syncthreads();
#pragma unroll
        for (int r = 0; r < 16; r++)
#pragma unroll
            for (int j = 0; j < 9; j++) acc[j] += ks[r][od[j]] * vs[r][oe[j]];
    }
#pragma unroll
    for (int j = 0; j < 9; j++)
        atomicAdd(&g_kv[b * 5184 + tid + j * 576], acc[j]);

#pragma unroll
    for (int o = 16; o; o >>= 1) {
        k2 += __shfl_down_sync(0xffffffffu, k2, o);
        k6 += __shfl_down_sync(0xffffffffu, k6, o);
    }
    int w = tid >> 5, l = tid & 31;
    if (l == 0) { rsh2[w] = k2; rsh6[w] = k6; }
    __syncthreads();
    if (tid == 0) {
        float a = 0.f, c = 0.f;
#pragma unroll
        for (int i = 0; i < 18; i++) { a += rsh2[i]; c += rsh6[i]; }
        atomicAdd(&g_ksum[b * 2], a);
        atomicAdd(&g_ksum[b * 2 + 1], c);
    }
}

// ---------------- depthwise conv -> A2 cols [C_, KA2) (fp16) -----------------
__global__ void k_dwc(const float* __restrict__ w, const float* __restrict__ bias) {
    int idx = blockIdx.x * blockDim.x + threadIdx.x;
    int d = idx % HD_;
    int t = idx / HD_;
    int n = t % N_;
    int b = t / N_;
    int y = n >> 6, xx = n & 63;
    float acc = bias[d];
#pragma unroll
    for (int ky = 0; ky < 3; ky++) {
        int yy = y + ky - 1;
        if ((unsigned)yy < 64u) {
#pragma unroll
            for (int kx = 0; kx < 3; kx++) {
                int xc = xx + kx - 1;
                if ((unsigned)xc < 64u)
                    acc += g_kvlin[(size_t)(b * N_ + yy * 64 + xc) * KV2 + 72 + d]
                         * w[d * 9 + ky * 3 + kx];
            }
        }
    }
    g_A2h[(size_t)(b * N_ + n) * KA2 + C_ + d] = __float2half(acc);
}

// ---------------- proj_sum -> B2 rows [C_, KA2) (fp16) -----------------------
__global__ void k_projsum(const float* __restrict__ proj) {
    int idx = blockIdx.x * blockDim.x + threadIdx.x;   // 72*1152
    if (idx >= HD_ * C_) return;
    int c = idx / HD_, d = idx % HD_;
    float s = 0.f;
#pragma unroll
    for (int h = 0; h < H_; h++) s += proj[(size_t)(h * HD_ + d) * C_ + c];
    __half hv = __float2half(s);
#pragma unroll
    for (int b = 0; b < B_; b++)
        g_B2h[((size_t)b * C_ + c) * KA2 + C_ + d] = hv;
}

// Mt[b][c][h*72+d] = scaleq[b,h]*scalek[b] * sum_e kv[b][d][e]*proj[h*72+e][c]
__global__ __launch_bounds__(256) void k_mker(const float* __restrict__ proj) {
    __shared__ float kvs[72 * 72];
    int b = blockIdx.z, h = blockIdx.y, ct = blockIdx.x;
    int tid = threadIdx.x;
    for (int e = tid; e < 5184; e += 256) kvs[e] = g_kv[b * 5184 + e];
    __syncthreads();
    int c = ct * 128 + (tid & 127);
    int dbase = (tid >> 7) * 36;
    float acc[36] = {};
#pragma unroll 8
    for (int e2 = 0; e2 < 72; e2++) {
        float p = proj[(size_t)(h * HD_ + e2) * C_ + c];
#pragma unroll
        for (int dd = 0; dd < 36; dd++)
            acc[dd] += kvs[(dbase + dd) * 72 + e2] * p;
    }
    float q2 = g_qsum[(b * H_ + h) * 2], q6 = g_qsum[(b * H_ + h) * 2 + 1];
    float kk2 = g_ksum[b * 2], kk6 = g_ksum[b * 2 + 1];
    float sq = ((q6 > 0.f) ? sqrtf(q2 / q6) : 0.f)
             * ((kk6 > 0.f) ? sqrtf(kk2 / kk6) : 0.f);
    size_t base = ((size_t)b * C_ + c) * KA2 + h * HD_ + dbase;
#pragma unroll
    for (int dd = 0; dd < 36; dd++)
        g_B2h[base + dd] = __float2half(acc[dd] * sq);
}

// ---------------- launch ------------------------------------------------------
extern "C" void kernel_launch(void* const* d_in, const int* in_sizes, int n_in,
                              void* d_out, int out_size) {
    const float* x      = (const float*)d_in[0];
    const float* wq_w   = (const float*)d_in[1];
    const float* wq_b   = (const float*)d_in[2];
    const float* wkv_w  = (const float*)d_in[3];
    const float* wkv_b  = (const float*)d_in[4];
    const float* dwc_w  = (const float*)d_in[5];
    const float* dwc_b  = (const float*)d_in[6];
    const float* proj_w = (const float*)d_in[7];
    const float* proj_b = (const float*)d_in[8];
    float* out = (float*)d_out;

    cudaFuncSetAttribute(
        k_hgemm<__half, C_, 18, 1, C_, false, true>,
        cudaFuncAttributeMaxDynamicSharedMemorySize, SMEM_BYTES);
    cudaFuncSetAttribute(
        k_hgemm<__half, C_, 18, 1, KV2, true, true>,
        cudaFuncAttributeMaxDynamicSharedMemorySize, SMEM_BYTES);
    cudaFuncSetAttribute(
        k_hgemm<__half, KA2, 20, 1, C_, false, true>,
        cudaFuncAttributeMaxDynamicSharedMemorySize, SMEM_BYTES);

    __half *x16, *wqh, *wkvh, *a2h, *b2h;
    float *gq, *gkvlin;
    cudaGetSymbolAddress((void**)&x16,  g_X16);
    cudaGetSymbolAddress((void**)&wqh,  g_Wqh);
    cudaGetSymbolAddress((void**)&wkvh, g_Wkvh);
    cudaGetSymbolAddress((void**)&a2h,  g_A2h);
    cudaGetSymbolAddress((void**)&b2h,  g_B2h);
    cudaGetSymbolAddress((void**)&gq,     g_q);
    cudaGetSymbolAddress((void**)&gkvlin, g_kvlin);

    k_init<<<324, 256>>>();
    k_xcvt<<<(int)((MTOT * (size_t)C_) / 1024), 256>>>(x);   // 4 elems/thread
    k_wcvt<<<((C_ + KV2) * C_) / 256, 256>>>(wq_w, wkv_w);

    // q-GEMM: x @ wq -> g_q (fp32)   (fp16 single-pass, K=1152, KT=18)
    k_hgemm<__half, C_, 18, 1, C_, false, true>
        <<<dim3(9, 512, 1), 256, SMEM_BYTES>>>(
            x16, x16, wqh, wqh, gq, nullptr, wq_b, nullptr);

    // kv-GEMM: x @ wkv -> g_kvlin   (fp16 single-pass, K=1152, KT=18)
    k_hgemm<__half, C_, 18, 1, KV2, true, true>
        <<<dim3(2, 512, 1), 256, SMEM_BYTES>>>(
            x16, x16, wkvh, wkvh, nullptr, gkvlin, nullptr, wkv_b);

    k_qf3norm<<<4096, 256>>>();        // q3 (fp16) -> A2 + qsum (vectorized)
    k_kvacc<<<dim3(8, 16), 576>>>();   // kv accum + fused ksum
    k_dwc<<<18432, 256>>>(dwc_w, dwc_b);
    k_projsum<<<324, 256>>>(proj_w);
    k_mker<<<dim3(9, 16, 16), 256>>>(proj_w);   // inline scales, folds sq*sk

    // GEMM2: [q3|vd] @ [scaled Mt|Pt]^T + proj_b -> out  (fp16, K=1224, KT=20)
    k_hgemm<__half, KA2, 20, 1, C_, false, true>
        <<<dim3(9, 32, 16), 256, SMEM_BYTES>>>(
            a2h, a2h, b2h, b2h, out, nullptr, proj_b, nullptr);
}